// round 13
// baseline (speedup 1.0000x reference)
#include <cuda_runtime.h>
#include <cuda_bf16.h>
#include <cstdint>

// RoPE2D encoder: output = [cos_2d (HW x 128) ; sin_2d (HW x 128)], fp32.
// H = W = 512, DIM = 128. Channels [0,64) depend only on x, [64,128) only on y.
// CONVERGED final design (best measured total: 41.0us; kernel ~38.5-39.5us =
// LTS/HBM write-path chip cap ~6300 B/cyc, confirmed invariant across loads/
// issue/store-width/tiling/L2-policy experiments R2-R12).
// Single fused kernel: each lane computes its 4 channel values analytically
// (sincosf for the initial angle, then an angle-addition rotation across the
// 8 rows this warp writes). No tables, no second launch, no data loads except
// one 16B inv_freq read per thread.

#define RP_H 512
#define RP_W 512
#define RP_HW (RP_H * RP_W)
#define ROWS_PER_WARP 8

// Warp: fixed `which` (cos/sin), 8 consecutive positions p0..p0+7 (same y).
// Lane q = float4 chunk (4 channels) of the 128-channel row.
//   q<16 : x-half, channels 4q..4q+3, freq index (4q+j) mod 32, angle (x0+i)*f
//   q>=16: y-half, channels 64+4(q-16)..,  freq index (4(q-16)+j) mod 32, angle y*f
// x-lanes advance angle by f per row via rotation; y-lanes rotate by 0 (identity),
// so the whole warp runs one uniform instruction stream.
__global__ void __launch_bounds__(256) rope2d_fused(float4* __restrict__ out,
                                                    const float* __restrict__ inv_freq_x,
                                                    const float* __restrict__ inv_freq_y) {
    unsigned warp_in_block = threadIdx.x >> 5;
    unsigned q             = threadIdx.x & 31u;
    unsigned gw    = blockIdx.x * 8u + warp_in_block;   // 0..65535
    unsigned which = gw >> 15;                          // 0 = cos, 1 = sin
    unsigned rp    = gw & 32767u;
    unsigned p0    = rp * ROWS_PER_WARP;
    unsigned y     = p0 >> 9;
    unsigned x0    = p0 & 511u;

    bool is_x = (q < 16u);

    // (4*(q mod 16) + j) mod 32 == 4*(q mod 8) + j  -> aligned float4 at index q&7.
    const float4* tf = reinterpret_cast<const float4*>(is_x ? inv_freq_x : inv_freq_y);
    float4 f4 = __ldg(tf + (q & 7u));
    float fr[4] = {f4.x, f4.y, f4.z, f4.w};

    float pos  = is_x ? (float)x0 : (float)y;
    float step = is_x ? 1.0f : 0.0f;          // y-lanes: identity rotation

    float c[4], s[4], cf[4], sf[4];
    #pragma unroll
    for (int j = 0; j < 4; j++) {
        sincosf(pos * fr[j], &s[j], &c[j]);
        sincosf(step * fr[j], &sf[j], &cf[j]);
    }

    float4* row = out + (size_t)which * (RP_HW * 32u) + (size_t)p0 * 32u + q;

    #pragma unroll
    for (int i = 0; i < ROWS_PER_WARP; i++) {
        float4 val;
        val.x = which ? s[0] : c[0];
        val.y = which ? s[1] : c[1];
        val.z = which ? s[2] : c[2];
        val.w = which ? s[3] : c[3];
        __stcs(row, val);                      // streaming store, 512B/warp
        row += 32u;

        if (i < ROWS_PER_WARP - 1) {
            #pragma unroll
            for (int j = 0; j < 4; j++) {
                float cn = fmaf(c[j], cf[j], -s[j] * sf[j]);
                float sn = fmaf(s[j], cf[j],  c[j] * sf[j]);
                c[j] = cn;
                s[j] = sn;
            }
        }
    }
}

extern "C" void kernel_launch(void* const* d_in, const int* in_sizes, int n_in,
                              void* d_out, int out_size) {
    const float* inv_freq_x = (const float*)d_in[1];
    const float* inv_freq_y = (const float*)d_in[2];
    float4* out = (float4*)d_out;

    // 65536 warps = 2 (which) x 32768 row-groups; 8 warps/block -> 8192 blocks
    rope2d_fused<<<8192, 256>>>(out, inv_freq_x, inv_freq_y);
}

// round 14
// speedup vs baseline: 1.3449x; 1.3449x over previous
#include <cuda_runtime.h>
#include <cuda_bf16.h>
#include <cstdint>

// RoPE2D encoder: output = [cos_2d (HW x 128) ; sin_2d (HW x 128)], fp32.
// H = W = 512, DIM = 128. Channels [0,64) depend only on x, [64,128) only on y.
// FINAL design, selected for robustness across DVFS states:
// each warp handles 8 consecutive positions (same y) and stores BOTH the cos
// and sin rows (sincosf yields both), halving trig + index instructions per
// byte vs a which-split layout (issue 30% vs 65% at full clock). At full
// clock all variants ride the ~6300 B/cyc LTS write cap (~38.5us); under
// clock throttle (observed on this chip) the lowest-issue variant degrades
// least because issue/L1 become clock-domain limiters.
// Lane q = float4 chunk (4 channels): q<16 -> x-half (rotates by f per row),
// q>=16 -> y-half (identity rotation). Streaming float4 stores.

#define RP_H 512
#define RP_W 512
#define RP_HW (RP_H * RP_W)
#define ROWS_PER_WARP 8

__global__ void __launch_bounds__(256) rope2d_fused(float4* __restrict__ out,
                                                    const float* __restrict__ inv_freq_x,
                                                    const float* __restrict__ inv_freq_y) {
    unsigned warp_in_block = threadIdx.x >> 5;
    unsigned q             = threadIdx.x & 31u;
    unsigned gw  = blockIdx.x * 8u + warp_in_block;   // 0..32767
    unsigned p0  = gw * ROWS_PER_WARP;                // base position
    unsigned y   = p0 >> 9;
    unsigned x0  = p0 & 511u;

    bool is_x = (q < 16u);

    // channels 4*(q mod 16)+j ; freq index mod 32 -> aligned float4 at q&7.
    const float4* tf = reinterpret_cast<const float4*>(is_x ? inv_freq_x : inv_freq_y);
    float4 f4 = __ldg(tf + (q & 7u));
    float fr[4] = {f4.x, f4.y, f4.z, f4.w};

    float pos  = is_x ? (float)x0 : (float)y;
    float step = is_x ? 1.0f : 0.0f;          // y-lanes: identity rotation

    float c[4], s[4], cf[4], sf[4];
    #pragma unroll
    for (int j = 0; j < 4; j++) {
        sincosf(pos * fr[j], &s[j], &c[j]);
        sincosf(step * fr[j], &sf[j], &cf[j]);
    }

    float4* rowc = out + (size_t)p0 * 32u + q;                    // cos half
    float4* rows = rowc + (size_t)RP_HW * 32u;                    // sin half

    #pragma unroll
    for (int i = 0; i < ROWS_PER_WARP; i++) {
        float4 vc, vs;
        vc.x = c[0]; vc.y = c[1]; vc.z = c[2]; vc.w = c[3];
        vs.x = s[0]; vs.y = s[1]; vs.z = s[2]; vs.w = s[3];
        __stcs(rowc + (size_t)i * 32u, vc);   // 512B/warp, cos stream
        __stcs(rows + (size_t)i * 32u, vs);   // 512B/warp, sin stream

        if (i < ROWS_PER_WARP - 1) {
            #pragma unroll
            for (int j = 0; j < 4; j++) {
                float cn = fmaf(c[j], cf[j], -s[j] * sf[j]);
                float sn = fmaf(s[j], cf[j],  c[j] * sf[j]);
                c[j] = cn;
                s[j] = sn;
            }
        }
    }
}

extern "C" void kernel_launch(void* const* d_in, const int* in_sizes, int n_in,
                              void* d_out, int out_size) {
    const float* inv_freq_x = (const float*)d_in[1];
    const float* inv_freq_y = (const float*)d_in[2];
    float4* out = (float4*)d_out;

    // 32768 warps x 8 positions = 262144 positions; 8 warps/block -> 4096 blocks
    rope2d_fused<<<4096, 256>>>(out, inv_freq_x, inv_freq_y);
}